// round 6
// baseline (speedup 1.0000x reference)
#include <cuda_runtime.h>
#include <cuda_bf16.h>
#include <cstdint>

#define BB   8
#define NCAM 6
#define DD   41
#define FHH  8
#define FWW  22
#define CC   64
#define NXY  200
#define PTS_PER_CAM (DD*FHH*FWW)          /* 7216 */
#define NPTS (BB*NCAM*PTS_PER_CAM)        /* 346368 */
#define GRID_CELLS (BB*NXY*NXY)           /* 320000 */
#define NCAMS (BB*NCAM)                   /* 48 */
#define BLKS_PER_CAM (PTS_PER_CAM/16)     /* 451: 16 points per 256-thread block */

// Scratch: channel-last voxel grid [B,200,200,C]  (81.92 MB, static device alloc)
// INVARIANT: all-zero at the start of every kernel_launch call. Static init
// zeroes it; transpose_out re-zeroes every touched cell after reading it.
__device__ float g_scratch[(size_t)GRID_CELLS * CC];
// Per-cell touched flag. INVARIANT: all-zero at call start; scatter sets,
// transpose_out reads + clears.
__device__ unsigned g_count[GRID_CELLS];

// ---------------------------------------------------------------------------
// Reciprocal without div.rn.f64: f32 estimate + 2 double Newton steps
// (< 1 double ulp — invisible after the final cast to f32).
__device__ __forceinline__ double rcp_newton(double d) {
    double r = (double)__frcp_rn((float)d);
    double e = fma(-d, r, 1.0);  r = fma(r, e, r);
    e        = fma(-d, r, 1.0);  r = fma(r, e, r);
    return r;
}

// ---------------------------------------------------------------------------
// Fused camera-setup + voxelize + scatter-add.
// Every block covers exactly 16 points of ONE camera (7216 = 16*451), so the
// block computes its camera's fused params in shared memory as a prologue:
//   scp[0:9)  = inv(post_rots)   scp[9:12)  = post_trans
//   scp[12:21)= rots@inv(intrins) scp[21:24) = trans
// ~450 f64 ops per block, hidden under the kernel's memory latency.
__global__ void scatter(const float* __restrict__ x_feats,
                        const float* __restrict__ rots,
                        const float* __restrict__ trans,
                        const float* __restrict__ intrins,
                        const float* __restrict__ post_rots,
                        const float* __restrict__ post_trans) {
    __shared__ float  scp[24];
    __shared__ double sik[9];            // inv(intrins), double
    int t   = threadIdx.x;               // 256 threads
    int cam = blockIdx.x / BLKS_PER_CAM;

    if (t < 18) {
        int m = t / 9;                   // 0: post_rots, 1: intrins
        int j = t - m * 9;
        int r = j / 3, c = j - r * 3;
        const float* src = (m == 0 ? post_rots : intrins) + cam * 9;
        double a[9];
        #pragma unroll
        for (int k = 0; k < 9; k++) a[k] = src[k];
        double det = a[0]*(a[4]*a[8] - a[5]*a[7])
                   + a[1]*(a[5]*a[6] - a[3]*a[8])
                   + a[2]*(a[3]*a[7] - a[4]*a[6]);
        double id = rcp_newton(det);
        int c1 = (c + 1) % 3, c2 = (c + 2) % 3;
        int r1 = (r + 1) % 3, r2 = (r + 2) % 3;
        double adj = a[c1*3 + r1] * a[c2*3 + r2]
                   - a[c1*3 + r2] * a[c2*3 + r1];
        double v = adj * id;
        if (m == 0) scp[j] = (float)v;
        else        sik[j] = v;
    } else if (t < 21) {
        int j = t - 18;
        scp[9 + j]  = post_trans[cam*3 + j];
        scp[21 + j] = trans[cam*3 + j];
    }
    __syncthreads();
    if (t < 9) {
        int r = t / 3, c = t - r * 3;
        const float* rt = rots + cam * 9;
        double s = (double)rt[r*3+0] * sik[0*3 + c]
                 + (double)rt[r*3+1] * sik[1*3 + c]
                 + (double)rt[r*3+2] * sik[2*3 + c];
        scp[12 + t] = (float)s;
    }
    __syncthreads();

    int gid = blockIdx.x * blockDim.x + threadIdx.x;   // exact grid, no guard
    int point = gid >> 4;
    int c4    = gid & 15;

    int r   = point - cam * PTS_PER_CAM;
    int d   = r / (FHH * FWW);
    int r2  = r - d * (FHH * FWW);
    int h   = r2 / FWW;
    int w   = r2 - h * FWW;

    const float XSTEP = 351.0f / 21.0f;   // matches f32 linspace step
    const float YSTEP = 127.0f / 7.0f;
    float fx = (float)w * XSTEP;
    float fy = (float)h * YSTEP;
    float fz = 4.0f + (float)d;

    float px = fx - scp[9];
    float py = fy - scp[10];
    float pz = fz - scp[11];
    // q = inv(post_rots) @ p   (fma chain, k-order accumulation)
    float q0 = fmaf(scp[2], pz, fmaf(scp[1], py, scp[0]*px));
    float q1 = fmaf(scp[5], pz, fmaf(scp[4], py, scp[3]*px));
    float q2 = fmaf(scp[8], pz, fmaf(scp[7], py, scp[6]*px));
    // unproject: (u*d, v*d, d)
    float r0 = q0 * q2;
    float r1 = q1 * q2;
    float r2v = q2;
    // geom = combine @ r + trans
    float g0 = fmaf(scp[14], r2v, fmaf(scp[13], r1, scp[12]*r0)) + scp[21];
    float g1 = fmaf(scp[17], r2v, fmaf(scp[16], r1, scp[15]*r0)) + scp[22];
    float g2 = fmaf(scp[20], r2v, fmaf(scp[19], r1, scp[18]*r0)) + scp[23];

    // quantize: (geom - (BX - DX/2)) / DX, truncate toward zero
    float v0 = (g0 + 50.0f) / 0.5f;
    float v1 = (g1 + 50.0f) / 0.5f;
    float v2 = (g2 + 10.0f) / 20.0f;
    int i0 = (int)v0;
    int i1 = (int)v1;
    int i2 = (int)v2;

    if (i0 < 0 || i0 >= NXY || i1 < 0 || i1 >= NXY || i2 != 0) return;
    int b   = cam / NCAM;
    int vox = (b * NXY + i0) * NXY + i1;

    if (c4 == 0) g_count[vox] = 1u;   // benign race: all writers store 1
    float4 f = reinterpret_cast<const float4*>(x_feats)[gid];
    float* dst = g_scratch + (unsigned)vox * CC + c4 * 4;
    asm volatile("red.global.add.v4.f32 [%0], {%1,%2,%3,%4};"
                 :: "l"(dst), "f"(f.x), "f"(f.y), "f"(f.z), "f"(f.w)
                 : "memory");
}

// ---------------------------------------------------------------------------
// Transpose [B,200(x),200(y),C] -> out [B,C,200(x),200(y)].
// Per-cell skip: untouched cells contribute constant zero without any scratch
// read or re-zero. Touched cells are read once and zeroed behind the read
// (maintains the all-zero invariant). g_count is always cleared.
// All addressing in 32-bit (out: 20.48M elems, scratch: 5.12M float4s).
__global__ void transpose_out(float* __restrict__ out) {
    __shared__ float tile[32][65];
    __shared__ unsigned s_flag[32];
    __shared__ int s_touched;
    int tid = threadIdx.x;               // 256 threads
    int bx  = blockIdx.y;                // b*200 + x
    int y0  = blockIdx.x * 32;
    int b = bx / NXY;
    int x = bx - b * NXY;
    int cellbase = bx * NXY;

    if (tid < 32) {
        int y = y0 + tid;
        unsigned f = 0u;
        if (y < NXY) {
            f = g_count[cellbase + y];
            if (f) g_count[cellbase + y] = 0u;
        }
        s_flag[tid] = f;
        unsigned m = __ballot_sync(0xffffffffu, f != 0u);
        if (tid == 0) s_touched = (m != 0u);
    }
    __syncthreads();

    int lane = tid & 31;
    int warp = tid >> 5;                 // 0..7
    int cgrp = lane >> 3;                // 0..3
    int yseg = lane & 7;                 // 0..7
    int yg4  = y0 + yseg * 4;            // float4-aligned y

    float4* out4 = reinterpret_cast<float4*>(out);

    if (s_touched) {
        // Load 32y x 64c tile as float4; skip + keep-zero for untouched cells.
        float4* srcbase = reinterpret_cast<float4*>(g_scratch) + (unsigned)cellbase * 16;
        int c4  = tid & 15;
        int ylo = tid >> 4;              // 0..15
        #pragma unroll
        for (int i = 0; i < 2; i++) {
            int y  = ylo + 16 * i;
            int yg = y0 + y;
            if (yg < NXY) {
                float4 v = make_float4(0.f, 0.f, 0.f, 0.f);
                if (s_flag[y]) {
                    v = srcbase[yg * 16 + c4];
                    srcbase[yg * 16 + c4] = make_float4(0.f, 0.f, 0.f, 0.f);
                }
                tile[y][c4 * 4 + 0] = v.x;
                tile[y][c4 * 4 + 1] = v.y;
                tile[y][c4 * 4 + 2] = v.z;
                tile[y][c4 * 4 + 3] = v.w;
            }
        }
        __syncthreads();
        if (yg4 < NXY) {
            #pragma unroll
            for (int j = 0; j < 2; j++) {
                int c = warp * 4 + cgrp + j * 32;
                int yl = yseg * 4;
                float4 v;
                v.x = tile[yl + 0][c];
                v.y = tile[yl + 1][c];
                v.z = tile[yl + 2][c];
                v.w = tile[yl + 3][c];
                unsigned o4 = ((((unsigned)b * CC + c) * NXY + x) * NXY + yg4) >> 2;
                out4[o4] = v;
            }
        }
    } else {
        if (yg4 < NXY) {
            float4 z = make_float4(0.f, 0.f, 0.f, 0.f);
            #pragma unroll
            for (int j = 0; j < 2; j++) {
                int c = warp * 4 + cgrp + j * 32;
                unsigned o4 = ((((unsigned)b * CC + c) * NXY + x) * NXY + yg4) >> 2;
                out4[o4] = z;
            }
        }
    }
}

// ---------------------------------------------------------------------------
extern "C" void kernel_launch(void* const* d_in, const int* in_sizes, int n_in,
                              void* d_out, int out_size) {
    const float* x_feats    = (const float*)d_in[0];
    const float* rots       = (const float*)d_in[1];
    const float* trans      = (const float*)d_in[2];
    const float* intrins    = (const float*)d_in[3];
    const float* post_rots  = (const float*)d_in[4];
    const float* post_trans = (const float*)d_in[5];
    float* out = (float*)d_out;

    scatter<<<NPTS * 16 / 256, 256>>>(x_feats, rots, trans, intrins,
                                      post_rots, post_trans);
    transpose_out<<<dim3(7, BB * NXY), 256>>>(out);
}

// round 7
// speedup vs baseline: 1.0225x; 1.0225x over previous
#include <cuda_runtime.h>
#include <cuda_bf16.h>
#include <cstdint>

#define BB   8
#define NCAM 6
#define DD   41
#define FHH  8
#define FWW  22
#define CC   64
#define NXY  200
#define PTS_PER_CAM (DD*FHH*FWW)          /* 7216 */
#define NPTS (BB*NCAM*PTS_PER_CAM)        /* 346368 */
#define GRID_CELLS (BB*NXY*NXY)           /* 320000 */
#define NCAMS (BB*NCAM)                   /* 48 */

// Scratch: channel-last voxel grid [B,200,200,C]  (81.92 MB, static device alloc)
// INVARIANT: all-zero at the start of every kernel_launch call. Static init
// zeroes it; transpose_out re-zeroes every touched cell after reading it.
__device__ float g_scratch[(size_t)GRID_CELLS * CC];
// Per-cell touched flag. INVARIANT: all-zero at call start; scatter sets,
// transpose_out reads + clears.
__device__ unsigned g_count[GRID_CELLS];
// Per-camera fused params: inv(post_rots)[9], post_trans[3], combine[9], trans[3]
__device__ float g_cam[NCAMS][24];
// Param-ready flag. INVARIANT: 0 at call start; scatter block 0 sets,
// transpose_out resets.
__device__ unsigned g_ready;

// ---------------------------------------------------------------------------
// Reciprocal without div.rn.f64: f32 estimate + 2 double Newton steps
// (< 1 double ulp — invisible after the final cast to f32).
__device__ __forceinline__ double rcp_newton(double d) {
    double r = (double)__frcp_rn((float)d);
    double e = fma(-d, r, 1.0);  r = fma(r, e, r);
    e        = fma(-d, r, 1.0);  r = fma(r, e, r);
    return r;
}

// ---------------------------------------------------------------------------
// Fused camera-setup (block 0 only) + voxelize + scatter-add.
// Block 0 computes all 48 cameras' fused params once into g_cam, then raises
// g_ready. Other blocks prefetch their feature vector (independent of params),
// poll g_ready briefly, and proceed. transpose_out resets g_ready.
__global__ void __launch_bounds__(256, 8)
scatter(const float* __restrict__ x_feats,
        const float* __restrict__ rots,
        const float* __restrict__ trans,
        const float* __restrict__ intrins,
        const float* __restrict__ post_rots,
        const float* __restrict__ post_trans) {
    __shared__ double sik[NCAMS][9];     // inv(intrins) (block 0 only)
    int t   = threadIdx.x;               // 256 threads
    int gid = blockIdx.x * 256 + t;      // exact grid, no guard

    // Prefetch feature vector — independent of camera params, overlaps wait.
    float4 f = reinterpret_cast<const float4*>(x_feats)[gid];

    if (blockIdx.x == 0) {
        // --- compute camera params (same math/order as R5 cam_setup) ---
        if (t < 2 * NCAMS) {
            int role = t / NCAMS;        // 0: post_rots, 1: intrins
            int cam  = t - role * NCAMS;
            const float* src = (role == 0 ? post_rots : intrins) + cam * 9;
            double a[9];
            #pragma unroll
            for (int k = 0; k < 9; k++) a[k] = src[k];
            double det = a[0]*(a[4]*a[8] - a[5]*a[7])
                       + a[1]*(a[5]*a[6] - a[3]*a[8])
                       + a[2]*(a[3]*a[7] - a[4]*a[6]);
            double id = rcp_newton(det);
            #pragma unroll
            for (int r = 0; r < 3; r++) {
                #pragma unroll
                for (int c = 0; c < 3; c++) {
                    int c1 = (c + 1) % 3, c2 = (c + 2) % 3;
                    int r1 = (r + 1) % 3, r2 = (r + 2) % 3;
                    double adj = a[c1*3 + r1] * a[c2*3 + r2]
                               - a[c1*3 + r2] * a[c2*3 + r1];
                    double v = adj * id;
                    if (role == 0) g_cam[cam][r*3 + c] = (float)v;
                    else           sik[cam][r*3 + c]   = v;
                }
            }
            if (role == 0) {
                #pragma unroll
                for (int j = 0; j < 3; j++) {
                    g_cam[cam][9 + j]  = post_trans[cam*3 + j];
                    g_cam[cam][21 + j] = trans[cam*3 + j];
                }
            }
        }
        __syncthreads();
        if (t < NCAMS) {
            const float* rt = rots + t * 9;
            #pragma unroll
            for (int r = 0; r < 3; r++) {
                #pragma unroll
                for (int c = 0; c < 3; c++) {
                    double s = (double)rt[r*3+0] * sik[t][0*3 + c]
                             + (double)rt[r*3+1] * sik[t][1*3 + c]
                             + (double)rt[r*3+2] * sik[t][2*3 + c];
                    g_cam[t][12 + r*3 + c] = (float)s;
                }
            }
        }
        __threadfence();
        __syncthreads();
        if (t == 0) atomicExch(&g_ready, 1u);
    } else {
        if (t == 0) {
            while (atomicOr(&g_ready, 0u) == 0u) __nanosleep(128);
            __threadfence();
        }
        __syncthreads();
    }

    int point = gid >> 4;
    int c4    = gid & 15;

    int cam = point / PTS_PER_CAM;
    int r   = point - cam * PTS_PER_CAM;
    int d   = r / (FHH * FWW);
    int r2  = r - d * (FHH * FWW);
    int h   = r2 / FWW;
    int w   = r2 - h * FWW;

    const float* cp = g_cam[cam];
    const float XSTEP = 351.0f / 21.0f;   // matches f32 linspace step
    const float YSTEP = 127.0f / 7.0f;
    float fx = (float)w * XSTEP;
    float fy = (float)h * YSTEP;
    float fz = 4.0f + (float)d;

    float px = fx - cp[9];
    float py = fy - cp[10];
    float pz = fz - cp[11];
    // q = inv(post_rots) @ p   (fma chain, k-order accumulation)
    float q0 = fmaf(cp[2], pz, fmaf(cp[1], py, cp[0]*px));
    float q1 = fmaf(cp[5], pz, fmaf(cp[4], py, cp[3]*px));
    float q2 = fmaf(cp[8], pz, fmaf(cp[7], py, cp[6]*px));
    // unproject: (u*d, v*d, d)
    float r0 = q0 * q2;
    float r1 = q1 * q2;
    float r2v = q2;
    // geom = combine @ r + trans
    float g0 = fmaf(cp[14], r2v, fmaf(cp[13], r1, cp[12]*r0)) + cp[21];
    float g1 = fmaf(cp[17], r2v, fmaf(cp[16], r1, cp[15]*r0)) + cp[22];
    float g2 = fmaf(cp[20], r2v, fmaf(cp[19], r1, cp[18]*r0)) + cp[23];

    // quantize: (geom - (BX - DX/2)) / DX, truncate toward zero
    float v0 = (g0 + 50.0f) / 0.5f;
    float v1 = (g1 + 50.0f) / 0.5f;
    float v2 = (g2 + 10.0f) / 20.0f;
    int i0 = (int)v0;
    int i1 = (int)v1;
    int i2 = (int)v2;

    if (i0 < 0 || i0 >= NXY || i1 < 0 || i1 >= NXY || i2 != 0) return;
    int b   = cam / NCAM;
    int vox = (b * NXY + i0) * NXY + i1;

    if (c4 == 0) g_count[vox] = 1u;   // benign race: all writers store 1
    float* dst = g_scratch + (unsigned)vox * CC + c4 * 4;
    asm volatile("red.global.add.v4.f32 [%0], {%1,%2,%3,%4};"
                 :: "l"(dst), "f"(f.x), "f"(f.y), "f"(f.z), "f"(f.w)
                 : "memory");
}

// ---------------------------------------------------------------------------
// Transpose [B,200(x),200(y),C] -> out [B,C,200(x),200(y)].
// One block handles FOUR bx rows (4 x 32y x 64c tiles) to raise per-thread
// MLP (up to 8 independent float4 loads before one barrier) and amortize
// barriers. Per-cell skip: untouched cells contribute zero without scratch
// read or re-zero. Touched cells are read once and zeroed behind the read.
// g_count always cleared; g_ready reset here.
__global__ void transpose_out(float* __restrict__ out) {
    __shared__ float tile[4][32][65];
    __shared__ unsigned s_flag[4][32];
    __shared__ unsigned s_touch[4];
    int tid = threadIdx.x;               // 256 threads
    int xg  = blockIdx.y;                // 0..399 -> 4 consecutive bx
    int y0  = blockIdx.x * 32;
    int bx0 = xg * 4;
    int b   = bx0 / NXY;                 // 200 % 4 == 0: group never crosses b
    int x0  = bx0 - b * NXY;

    if (blockIdx.x == 0 && blockIdx.y == 0 && tid == 0) g_ready = 0u;

    if (tid < 128) {
        int u  = tid >> 5;
        int yl = tid & 31;
        int y  = y0 + yl;
        unsigned fl = 0u;
        if (y < NXY) {
            int cell = (bx0 + u) * NXY + y;
            fl = g_count[cell];
            if (fl) g_count[cell] = 0u;
        }
        s_flag[u][yl] = fl;
        unsigned m = __ballot_sync(0xffffffffu, fl != 0u);
        if (yl == 0) s_touch[u] = m;
    }
    __syncthreads();

    // Load phase: each thread covers (c4, ylo) and (c4, ylo+16) for all 4 rows.
    int c4  = tid & 15;
    int ylo = tid >> 4;                  // 0..15
    float4* sc4 = reinterpret_cast<float4*>(g_scratch);
    #pragma unroll
    for (int u = 0; u < 4; u++) {
        if (!s_touch[u]) continue;       // tile[u] stale; store phase writes zeros
        #pragma unroll
        for (int i = 0; i < 2; i++) {
            int yl = ylo + 16 * i;
            int yg = y0 + yl;
            if (yg < NXY) {
                float4 v = make_float4(0.f, 0.f, 0.f, 0.f);
                if (s_flag[u][yl]) {
                    unsigned idx = (unsigned)((bx0 + u) * NXY + yg) * 16 + c4;
                    v = sc4[idx];
                    sc4[idx] = make_float4(0.f, 0.f, 0.f, 0.f);
                }
                tile[u][yl][c4 * 4 + 0] = v.x;
                tile[u][yl][c4 * 4 + 1] = v.y;
                tile[u][yl][c4 * 4 + 2] = v.z;
                tile[u][yl][c4 * 4 + 3] = v.w;
            }
        }
    }
    __syncthreads();

    // Store phase: float4 along y, fully coalesced; conflict-free smem reads.
    int lane = tid & 31;
    int warp = tid >> 5;                 // 0..7
    int cgrp = lane >> 3;                // 0..3
    int yseg = lane & 7;                 // 0..7
    int yg4  = y0 + yseg * 4;
    float4* out4 = reinterpret_cast<float4*>(out);

    if (yg4 < NXY) {
        #pragma unroll
        for (int u = 0; u < 4; u++) {
            int x = x0 + u;
            bool tch = (s_touch[u] != 0u);
            #pragma unroll
            for (int j = 0; j < 2; j++) {
                int c = warp * 4 + cgrp + j * 32;
                float4 v = make_float4(0.f, 0.f, 0.f, 0.f);
                if (tch) {
                    int yl = yseg * 4;
                    v.x = tile[u][yl + 0][c];
                    v.y = tile[u][yl + 1][c];
                    v.z = tile[u][yl + 2][c];
                    v.w = tile[u][yl + 3][c];
                }
                unsigned o4 = ((((unsigned)b * CC + c) * NXY + x) * NXY + yg4) >> 2;
                out4[o4] = v;
            }
        }
    }
}

// ---------------------------------------------------------------------------
extern "C" void kernel_launch(void* const* d_in, const int* in_sizes, int n_in,
                              void* d_out, int out_size) {
    const float* x_feats    = (const float*)d_in[0];
    const float* rots       = (const float*)d_in[1];
    const float* trans      = (const float*)d_in[2];
    const float* intrins    = (const float*)d_in[3];
    const float* post_rots  = (const float*)d_in[4];
    const float* post_trans = (const float*)d_in[5];
    float* out = (float*)d_out;

    scatter<<<NPTS * 16 / 256, 256>>>(x_feats, rots, trans, intrins,
                                      post_rots, post_trans);
    transpose_out<<<dim3(7, 400), 256>>>(out);
}

// round 8
// speedup vs baseline: 1.8352x; 1.7949x over previous
#include <cuda_runtime.h>
#include <cuda_bf16.h>
#include <cstdint>

#define BB   8
#define NCAM 6
#define DD   41
#define FHH  8
#define FWW  22
#define CC   64
#define NXY  200
#define PTS_PER_CAM (DD*FHH*FWW)          /* 7216 */
#define NPTS (BB*NCAM*PTS_PER_CAM)        /* 346368 */
#define GRID_CELLS (BB*NXY*NXY)           /* 320000 */
#define NCAMS (BB*NCAM)                   /* 48 */

// Scratch: channel-last voxel grid [B,200,200,C]  (81.92 MB, static device alloc)
// INVARIANT: all-zero at the start of every kernel_launch call. Static init
// zeroes it; transpose_out re-zeroes every touched cell after reading it.
__device__ float g_scratch[(size_t)GRID_CELLS * CC];
// Per-cell touched flag. INVARIANT: all-zero at call start; scatter sets,
// transpose_out reads + clears.
__device__ unsigned g_count[GRID_CELLS];
// Per-camera fused params: inv(post_rots)[9], post_trans[3], combine[9], trans[3]
__device__ float g_cam[NCAMS][24];

// ---------------------------------------------------------------------------
// Reciprocal without div.rn.f64: f32 estimate + 2 double Newton steps
// (< 1 double ulp — invisible after the final cast to f32).
__device__ __forceinline__ double rcp_newton(double d) {
    double r = (double)__frcp_rn((float)d);
    double e = fma(-d, r, 1.0);  r = fma(r, e, r);
    e        = fma(-d, r, 1.0);  r = fma(r, e, r);
    return r;
}

// ---------------------------------------------------------------------------
// Camera setup: 96 threads, one 3x3 inverse each, no f64 divides.
// Triggers programmatic launch completion early so dependent kernels can
// begin launching/prefetching while this block drains.
__global__ void cam_setup(const float* __restrict__ rots,
                          const float* __restrict__ trans,
                          const float* __restrict__ intrins,
                          const float* __restrict__ post_rots,
                          const float* __restrict__ post_trans) {
    __shared__ double sik[NCAMS][9];     // inv(intrins)
    int t = threadIdx.x;                 // 0..95
    int role = t / NCAMS;                // 0: post_rots, 1: intrins
    int cam  = t - role * NCAMS;

    if (t < 2 * NCAMS) {
        const float* src = (role == 0 ? post_rots : intrins) + cam * 9;
        double a[9];
        #pragma unroll
        for (int k = 0; k < 9; k++) a[k] = src[k];
        double det = a[0]*(a[4]*a[8] - a[5]*a[7])
                   + a[1]*(a[5]*a[6] - a[3]*a[8])
                   + a[2]*(a[3]*a[7] - a[4]*a[6]);
        double id = rcp_newton(det);
        #pragma unroll
        for (int r = 0; r < 3; r++) {
            #pragma unroll
            for (int c = 0; c < 3; c++) {
                int c1 = (c + 1) % 3, c2 = (c + 2) % 3;
                int r1 = (r + 1) % 3, r2 = (r + 2) % 3;
                double adj = a[c1*3 + r1] * a[c2*3 + r2]
                           - a[c1*3 + r2] * a[c2*3 + r1];
                double v = adj * id;
                if (role == 0) g_cam[cam][r*3 + c] = (float)v;
                else           sik[cam][r*3 + c]   = v;
            }
        }
        if (role == 0) {
            #pragma unroll
            for (int j = 0; j < 3; j++) {
                g_cam[cam][9 + j]  = post_trans[cam*3 + j];
                g_cam[cam][21 + j] = trans[cam*3 + j];
            }
        }
    }
    __syncthreads();
    if (t < NCAMS) {
        const float* rt = rots + t * 9;
        #pragma unroll
        for (int r = 0; r < 3; r++) {
            #pragma unroll
            for (int c = 0; c < 3; c++) {
                double s = (double)rt[r*3+0] * sik[t][0*3 + c]
                         + (double)rt[r*3+1] * sik[t][1*3 + c]
                         + (double)rt[r*3+2] * sik[t][2*3 + c];
                g_cam[t][12 + r*3 + c] = (float)s;
            }
        }
    }
    cudaTriggerProgrammaticLaunchCompletion();
}

// ---------------------------------------------------------------------------
// Voxelize + scatter-add. 16 threads per point (one float4 of channels each).
// PDL: prefetch the feature vector (param-independent), then wait for
// cam_setup's grid before reading g_cam.
__global__ void scatter(const float* __restrict__ x_feats) {
    int gid = blockIdx.x * 256 + threadIdx.x;          // exact grid, no guard
    int point = gid >> 4;
    int c4    = gid & 15;

    // Prefetch (read-once stream: .cs hint keeps scratch resident in L2)
    float4 f = __ldcs(reinterpret_cast<const float4*>(x_feats) + gid);

    cudaGridDependencySynchronize();    // wait for cam_setup's writes

    int cam = point / PTS_PER_CAM;
    int r   = point - cam * PTS_PER_CAM;
    int d   = r / (FHH * FWW);
    int r2  = r - d * (FHH * FWW);
    int h   = r2 / FWW;
    int w   = r2 - h * FWW;

    const float* cp = g_cam[cam];
    const float XSTEP = 351.0f / 21.0f;   // matches f32 linspace step
    const float YSTEP = 127.0f / 7.0f;
    float fx = (float)w * XSTEP;
    float fy = (float)h * YSTEP;
    float fz = 4.0f + (float)d;

    float px = fx - cp[9];
    float py = fy - cp[10];
    float pz = fz - cp[11];
    // q = inv(post_rots) @ p   (fma chain, k-order accumulation)
    float q0 = fmaf(cp[2], pz, fmaf(cp[1], py, cp[0]*px));
    float q1 = fmaf(cp[5], pz, fmaf(cp[4], py, cp[3]*px));
    float q2 = fmaf(cp[8], pz, fmaf(cp[7], py, cp[6]*px));
    // unproject: (u*d, v*d, d)
    float r0 = q0 * q2;
    float r1 = q1 * q2;
    float r2v = q2;
    // geom = combine @ r + trans
    float g0 = fmaf(cp[14], r2v, fmaf(cp[13], r1, cp[12]*r0)) + cp[21];
    float g1 = fmaf(cp[17], r2v, fmaf(cp[16], r1, cp[15]*r0)) + cp[22];
    float g2 = fmaf(cp[20], r2v, fmaf(cp[19], r1, cp[18]*r0)) + cp[23];

    // quantize: (geom - (BX - DX/2)) / DX, truncate toward zero
    float v0 = (g0 + 50.0f) / 0.5f;
    float v1 = (g1 + 50.0f) / 0.5f;
    float v2 = (g2 + 10.0f) / 20.0f;
    int i0 = (int)v0;
    int i1 = (int)v1;
    int i2 = (int)v2;

    if (i0 < 0 || i0 >= NXY || i1 < 0 || i1 >= NXY || i2 != 0) return;
    int b   = cam / NCAM;
    int vox = (b * NXY + i0) * NXY + i1;

    if (c4 == 0) g_count[vox] = 1u;   // benign race: all writers store 1
    float* dst = g_scratch + (unsigned)vox * CC + c4 * 4;
    asm volatile("red.global.add.v4.f32 [%0], {%1,%2,%3,%4};"
                 :: "l"(dst), "f"(f.x), "f"(f.y), "f"(f.z), "f"(f.w)
                 : "memory");
}

// ---------------------------------------------------------------------------
// Transpose [B,200(x),200(y),C] -> out [B,C,200(x),200(y)].
// TWO bx rows per block (16.6 KB smem keeps full occupancy); per-cell skip via
// a per-tile ballot bitmask -> branch-free predicated LDG.128 (4 independent
// loads per thread). Touched cells are read once and zeroed behind the read
// (maintains the all-zero invariant). g_count always cleared.
__global__ void transpose_out(float* __restrict__ out) {
    __shared__ float tile[2][32][65];
    __shared__ unsigned s_touch[2];
    int tid = threadIdx.x;               // 256 threads
    int xg  = blockIdx.y;                // 0..799 -> 2 consecutive bx
    int y0  = blockIdx.x * 32;
    int bx0 = xg * 2;
    int b   = bx0 / NXY;                 // 200 % 2 == 0: never crosses b
    int x0  = bx0 - b * NXY;

    cudaGridDependencySynchronize();    // wait for scatter's atomics/flags

    if (tid < 64) {
        int u  = tid >> 5;
        int yl = tid & 31;
        int y  = y0 + yl;
        unsigned fl = 0u;
        if (y < NXY) {
            int cell = (bx0 + u) * NXY + y;
            fl = g_count[cell];
            if (fl) g_count[cell] = 0u;
        }
        unsigned m = __ballot_sync(0xffffffffu, fl != 0u);
        if (yl == 0) s_touch[u] = m;
    }
    __syncthreads();

    // Load phase: thread covers (c4, ylo) and (c4, ylo+16) for both rows.
    int c4  = tid & 15;
    int ylo = tid >> 4;                  // 0..15
    float4* sc4 = reinterpret_cast<float4*>(g_scratch);
    float4 z4 = make_float4(0.f, 0.f, 0.f, 0.f);
    #pragma unroll
    for (int u = 0; u < 2; u++) {
        unsigned m = s_touch[u];
        if (!m) continue;                // tile[u] stale; store phase emits zeros
        #pragma unroll
        for (int i = 0; i < 2; i++) {
            int yl = ylo + 16 * i;
            int yg = y0 + yl;
            bool live = (yg < NXY) && ((m >> yl) & 1u);
            float4 v = z4;
            unsigned idx = (unsigned)((bx0 + u) * NXY + yg) * 16 + c4;
            if (live) {
                v = __ldcs(sc4 + idx);
                __stcs(sc4 + idx, z4);
            }
            if (yg < NXY) {
                tile[u][yl][c4 * 4 + 0] = v.x;
                tile[u][yl][c4 * 4 + 1] = v.y;
                tile[u][yl][c4 * 4 + 2] = v.z;
                tile[u][yl][c4 * 4 + 3] = v.w;
            }
        }
    }
    __syncthreads();

    // Store phase: float4 along y, fully coalesced; conflict-free smem reads.
    int lane = tid & 31;
    int warp = tid >> 5;                 // 0..7
    int cgrp = lane >> 3;                // 0..3
    int yseg = lane & 7;                 // 0..7
    int yg4  = y0 + yseg * 4;
    float4* out4 = reinterpret_cast<float4*>(out);

    if (yg4 < NXY) {
        #pragma unroll
        for (int u = 0; u < 2; u++) {
            int x = x0 + u;
            bool tch = (s_touch[u] != 0u);
            #pragma unroll
            for (int j = 0; j < 2; j++) {
                int c = warp * 4 + cgrp + j * 32;
                float4 v = z4;
                if (tch) {
                    int yl = yseg * 4;
                    v.x = tile[u][yl + 0][c];
                    v.y = tile[u][yl + 1][c];
                    v.z = tile[u][yl + 2][c];
                    v.w = tile[u][yl + 3][c];
                }
                unsigned o4 = ((((unsigned)b * CC + c) * NXY + x) * NXY + yg4) >> 2;
                __stcs(out4 + o4, v);
            }
        }
    }
}

// ---------------------------------------------------------------------------
extern "C" void kernel_launch(void* const* d_in, const int* in_sizes, int n_in,
                              void* d_out, int out_size) {
    const float* x_feats    = (const float*)d_in[0];
    const float* rots       = (const float*)d_in[1];
    const float* trans      = (const float*)d_in[2];
    const float* intrins    = (const float*)d_in[3];
    const float* post_rots  = (const float*)d_in[4];
    const float* post_trans = (const float*)d_in[5];
    float* out = (float*)d_out;

    cam_setup<<<1, 96>>>(rots, trans, intrins, post_rots, post_trans);

    cudaLaunchAttribute attrs[1];
    attrs[0].id = cudaLaunchAttributeProgrammaticStreamSerialization;
    attrs[0].val.programmaticStreamSerializationAllowed = 1;

    cudaLaunchConfig_t cfg = {};
    cfg.gridDim  = dim3(NPTS * 16 / 256);
    cfg.blockDim = dim3(256);
    cfg.dynamicSmemBytes = 0;
    cfg.stream = 0;
    cfg.attrs = attrs;
    cfg.numAttrs = 1;
    cudaLaunchKernelEx(&cfg, scatter, x_feats);

    cudaLaunchConfig_t cfg2 = cfg;
    cfg2.gridDim = dim3(7, 800);
    cudaLaunchKernelEx(&cfg2, transpose_out, out);
}

// round 12
// speedup vs baseline: 1.9164x; 1.0442x over previous
#include <cuda_runtime.h>
#include <cuda_bf16.h>
#include <cstdint>

#define BB   8
#define NCAM 6
#define DD   41
#define FHH  8
#define FWW  22
#define CC   64
#define NXY  200
#define PTS_PER_CAM (DD*FHH*FWW)          /* 7216 */
#define NPTS (BB*NCAM*PTS_PER_CAM)        /* 346368 */
#define GRID_CELLS (BB*NXY*NXY)           /* 320000 */
#define NCAMS (BB*NCAM)                   /* 48 */
#define SCAT_BLOCKS (NPTS*16/256)         /* 21648 */
#define FILL_BLOCKS 1250                  /* 1250*4096 float4 = whole out */

// Scratch: channel-last voxel grid [B,200,200,C]  (81.92 MB, static device alloc)
// INVARIANT: all-zero at the start of every kernel_launch call. Static init
// zeroes it; transpose_out re-zeroes every touched cell after reading it.
__device__ float g_scratch[(size_t)GRID_CELLS * CC];
// Per-cell touched flag. INVARIANT: all-zero at call start; scatter sets,
// transpose_out reads + clears.
__device__ unsigned g_count[GRID_CELLS];
// Per-camera fused params: inv(post_rots)[9], post_trans[3], combine[9], trans[3]
__device__ float g_cam[NCAMS][24];

// ---------------------------------------------------------------------------
// Reciprocal without div.rn.f64: f32 estimate + 2 double Newton steps
// (< 1 double ulp — invisible after the final cast to f32).
__device__ __forceinline__ double rcp_newton(double d) {
    double r = (double)__frcp_rn((float)d);
    double e = fma(-d, r, 1.0);  r = fma(r, e, r);
    e        = fma(-d, r, 1.0);  r = fma(r, e, r);
    return r;
}

// ---------------------------------------------------------------------------
// Camera setup: 96 threads, one 3x3 inverse each, no f64 divides.
// PDL trigger at ENTRY: dependent blocks may launch immediately (fill blocks
// need no params; scatter blocks GridDependencySync before touching g_cam).
__global__ void cam_setup(const float* __restrict__ rots,
                          const float* __restrict__ trans,
                          const float* __restrict__ intrins,
                          const float* __restrict__ post_rots,
                          const float* __restrict__ post_trans) {
    cudaTriggerProgrammaticLaunchCompletion();
    __shared__ double sik[NCAMS][9];     // inv(intrins)
    int t = threadIdx.x;                 // 0..95
    int role = t / NCAMS;                // 0: post_rots, 1: intrins
    int cam  = t - role * NCAMS;

    if (t < 2 * NCAMS) {
        const float* src = (role == 0 ? post_rots : intrins) + cam * 9;
        double a[9];
        #pragma unroll
        for (int k = 0; k < 9; k++) a[k] = src[k];
        double det = a[0]*(a[4]*a[8] - a[5]*a[7])
                   + a[1]*(a[5]*a[6] - a[3]*a[8])
                   + a[2]*(a[3]*a[7] - a[4]*a[6]);
        double id = rcp_newton(det);
        #pragma unroll
        for (int r = 0; r < 3; r++) {
            #pragma unroll
            for (int c = 0; c < 3; c++) {
                int c1 = (c + 1) % 3, c2 = (c + 2) % 3;
                int r1 = (r + 1) % 3, r2 = (r + 2) % 3;
                double adj = a[c1*3 + r1] * a[c2*3 + r2]
                           - a[c1*3 + r2] * a[c2*3 + r1];
                double v = adj * id;
                if (role == 0) g_cam[cam][r*3 + c] = (float)v;
                else           sik[cam][r*3 + c]   = v;
            }
        }
        if (role == 0) {
            #pragma unroll
            for (int j = 0; j < 3; j++) {
                g_cam[cam][9 + j]  = post_trans[cam*3 + j];
                g_cam[cam][21 + j] = trans[cam*3 + j];
            }
        }
    }
    __syncthreads();
    if (t < NCAMS) {
        const float* rt = rots + t * 9;
        #pragma unroll
        for (int r = 0; r < 3; r++) {
            #pragma unroll
            for (int c = 0; c < 3; c++) {
                double s = (double)rt[r*3+0] * sik[t][0*3 + c]
                         + (double)rt[r*3+1] * sik[t][1*3 + c]
                         + (double)rt[r*3+2] * sik[t][2*3 + c];
                g_cam[t][12 + r*3 + c] = (float)s;
            }
        }
    }
}

// ---------------------------------------------------------------------------
// Fused output-zero-fill + voxelize + scatter-add.
// Blocks [0, FILL_BLOCKS) zero d_out (no camera dependency, no grid sync):
// they stream concurrently with cam_setup and the atomic phase. Remaining
// blocks: 16 threads per point, one float4 of channels each; prefetch the
// feature vector, then GridDependencySync before reading g_cam.
__global__ void scatter(const float* __restrict__ x_feats,
                        float* __restrict__ out) {
    int tid = threadIdx.x;               // 256 threads
    int bid = blockIdx.x;

    if (bid < FILL_BLOCKS) {
        float4* o4 = reinterpret_cast<float4*>(out);
        float4 z4 = make_float4(0.f, 0.f, 0.f, 0.f);
        int base = bid * 4096 + tid;
        #pragma unroll
        for (int i = 0; i < 16; i++)
            __stcs(o4 + base + i * 256, z4);
        return;
    }

    int gid = (bid - FILL_BLOCKS) * 256 + tid;   // exact grid, no guard
    int point = gid >> 4;
    int c4    = gid & 15;

    // Prefetch (read-once stream; keeps scratch resident in L2)
    float4 f = __ldcs(reinterpret_cast<const float4*>(x_feats) + gid);

    cudaGridDependencySynchronize();    // wait for cam_setup's writes

    int cam = point / PTS_PER_CAM;
    int r   = point - cam * PTS_PER_CAM;
    int d   = r / (FHH * FWW);
    int r2  = r - d * (FHH * FWW);
    int h   = r2 / FWW;
    int w   = r2 - h * FWW;

    const float* cp = g_cam[cam];
    const float XSTEP = 351.0f / 21.0f;   // matches f32 linspace step
    const float YSTEP = 127.0f / 7.0f;
    float fx = (float)w * XSTEP;
    float fy = (float)h * YSTEP;
    float fz = 4.0f + (float)d;

    float px = fx - cp[9];
    float py = fy - cp[10];
    float pz = fz - cp[11];
    // q = inv(post_rots) @ p   (fma chain, k-order accumulation)
    float q0 = fmaf(cp[2], pz, fmaf(cp[1], py, cp[0]*px));
    float q1 = fmaf(cp[5], pz, fmaf(cp[4], py, cp[3]*px));
    float q2 = fmaf(cp[8], pz, fmaf(cp[7], py, cp[6]*px));
    // unproject: (u*d, v*d, d)
    float r0 = q0 * q2;
    float r1 = q1 * q2;
    float r2v = q2;
    // geom = combine @ r + trans
    float g0 = fmaf(cp[14], r2v, fmaf(cp[13], r1, cp[12]*r0)) + cp[21];
    float g1 = fmaf(cp[17], r2v, fmaf(cp[16], r1, cp[15]*r0)) + cp[22];
    float g2 = fmaf(cp[20], r2v, fmaf(cp[19], r1, cp[18]*r0)) + cp[23];

    // quantize: (geom - (BX - DX/2)) / DX, truncate toward zero
    float v0 = (g0 + 50.0f) / 0.5f;
    float v1 = (g1 + 50.0f) / 0.5f;
    float v2 = (g2 + 10.0f) / 20.0f;
    int i0 = (int)v0;
    int i1 = (int)v1;
    int i2 = (int)v2;

    if (i0 < 0 || i0 >= NXY || i1 < 0 || i1 >= NXY || i2 != 0) return;
    int b   = cam / NCAM;
    int vox = (b * NXY + i0) * NXY + i1;

    if (c4 == 0) g_count[vox] = 1u;   // benign race: all writers store 1
    float* dst = g_scratch + (unsigned)vox * CC + c4 * 4;
    asm volatile("red.global.add.v4.f32 [%0], {%1,%2,%3,%4};"
                 :: "l"(dst), "f"(f.x), "f"(f.y), "f"(f.z), "f"(f.w)
                 : "memory");
}

// ---------------------------------------------------------------------------
// Transpose [B,200(x),200(y),C] -> out [B,C,200(x),200(y)] — TOUCHED TILES
// ONLY. Untouched tiles were already zero-filled by scatter's fill blocks:
// skip read AND write. Touched cells are read once and zeroed behind the
// read (maintains the all-zero scratch invariant). g_count always cleared.
__global__ void transpose_out(float* __restrict__ out) {
    __shared__ float tile[2][32][65];
    __shared__ unsigned s_touch[2];
    int tid = threadIdx.x;               // 256 threads
    int xg  = blockIdx.y;                // 0..799 -> 2 consecutive bx
    int y0  = blockIdx.x * 32;
    int bx0 = xg * 2;
    int b   = bx0 / NXY;                 // 200 % 2 == 0: never crosses b
    int x0  = bx0 - b * NXY;

    cudaGridDependencySynchronize();    // wait for scatter's atomics/flags

    if (tid < 64) {
        int u  = tid >> 5;
        int yl = tid & 31;
        int y  = y0 + yl;
        unsigned fl = 0u;
        if (y < NXY) {
            int cell = (bx0 + u) * NXY + y;
            fl = g_count[cell];
            if (fl) g_count[cell] = 0u;
        }
        unsigned m = __ballot_sync(0xffffffffu, fl != 0u);
        if (yl == 0) s_touch[u] = m;
    }
    __syncthreads();

    if ((s_touch[0] | s_touch[1]) == 0u) return;   // fill already wrote zeros

    // Load phase: thread covers (c4, ylo) and (c4, ylo+16) for both rows.
    int c4  = tid & 15;
    int ylo = tid >> 4;                  // 0..15
    float4* sc4 = reinterpret_cast<float4*>(g_scratch);
    float4 z4 = make_float4(0.f, 0.f, 0.f, 0.f);
    #pragma unroll
    for (int u = 0; u < 2; u++) {
        unsigned m = s_touch[u];
        if (!m) continue;                // tile[u] stale; store phase skips it
        #pragma unroll
        for (int i = 0; i < 2; i++) {
            int yl = ylo + 16 * i;
            int yg = y0 + yl;
            bool live = (yg < NXY) && ((m >> yl) & 1u);
            float4 v = z4;
            unsigned idx = (unsigned)((bx0 + u) * NXY + yg) * 16 + c4;
            if (live) {
                v = __ldcs(sc4 + idx);
                __stcs(sc4 + idx, z4);
            }
            if (yg < NXY) {
                tile[u][yl][c4 * 4 + 0] = v.x;
                tile[u][yl][c4 * 4 + 1] = v.y;
                tile[u][yl][c4 * 4 + 2] = v.z;
                tile[u][yl][c4 * 4 + 3] = v.w;
            }
        }
    }
    __syncthreads();

    // Store phase: float4 along y, fully coalesced; conflict-free smem reads.
    int lane = tid & 31;
    int warp = tid >> 5;                 // 0..7
    int cgrp = lane >> 3;                // 0..3
    int yseg = lane & 7;                 // 0..7
    int yg4  = y0 + yseg * 4;
    float4* out4 = reinterpret_cast<float4*>(out);

    if (yg4 < NXY) {
        #pragma unroll
        for (int u = 0; u < 2; u++) {
            if (!s_touch[u]) continue;   // zeros already present from fill
            int x = x0 + u;
            #pragma unroll
            for (int j = 0; j < 2; j++) {
                int c = warp * 4 + cgrp + j * 32;
                int yl = yseg * 4;
                float4 v;
                v.x = tile[u][yl + 0][c];
                v.y = tile[u][yl + 1][c];
                v.z = tile[u][yl + 2][c];
                v.w = tile[u][yl + 3][c];
                unsigned o4 = ((((unsigned)b * CC + c) * NXY + x) * NXY + yg4) >> 2;
                __stcs(out4 + o4, v);
            }
        }
    }
}

// ---------------------------------------------------------------------------
extern "C" void kernel_launch(void* const* d_in, const int* in_sizes, int n_in,
                              void* d_out, int out_size) {
    const float* x_feats    = (const float*)d_in[0];
    const float* rots       = (const float*)d_in[1];
    const float* trans      = (const float*)d_in[2];
    const float* intrins    = (const float*)d_in[3];
    const float* post_rots  = (const float*)d_in[4];
    const float* post_trans = (const float*)d_in[5];
    float* out = (float*)d_out;

    cam_setup<<<1, 96>>>(rots, trans, intrins, post_rots, post_trans);

    cudaLaunchAttribute attrs[1];
    attrs[0].id = cudaLaunchAttributeProgrammaticStreamSerialization;
    attrs[0].val.programmaticStreamSerializationAllowed = 1;

    cudaLaunchConfig_t cfg = {};
    cfg.gridDim  = dim3(SCAT_BLOCKS + FILL_BLOCKS);
    cfg.blockDim = dim3(256);
    cfg.dynamicSmemBytes = 0;
    cfg.stream = 0;
    cfg.attrs = attrs;
    cfg.numAttrs = 1;
    cudaLaunchKernelEx(&cfg, scatter, x_feats, out);

    cudaLaunchConfig_t cfg2 = cfg;
    cfg2.gridDim = dim3(7, 800);
    cudaLaunchKernelEx(&cfg2, transpose_out, out);
}

// round 13
// speedup vs baseline: 2.5014x; 1.3052x over previous
#include <cuda_runtime.h>
#include <cuda_bf16.h>
#include <cstdint>

#define BB   8
#define NCAM 6
#define DD   41
#define FHH  8
#define FWW  22
#define CC   64
#define NXY  200
#define PTS_PER_CAM (DD*FHH*FWW)          /* 7216 */
#define NPTS (BB*NCAM*PTS_PER_CAM)        /* 346368 */
#define GRID_CELLS (BB*NXY*NXY)           /* 320000 */
#define NCAMS (BB*NCAM)                   /* 48 */
#define SCAT_BLOCKS (NPTS*8/256)          /* 10824: 8 lanes per point */
#define FILL_BLOCKS 1250                  /* 1250*4096 float4 = whole out */

// Scratch: channel-last voxel grid [B,200,200,C]  (81.92 MB, static device alloc)
// INVARIANT: all-zero at the start of every kernel_launch call. Static init
// zeroes it; transpose_out re-zeroes every touched cell after reading it.
__device__ float g_scratch[(size_t)GRID_CELLS * CC];
// Per-cell touched flag. INVARIANT: all-zero at call start; scatter sets,
// transpose_out reads + clears.
__device__ unsigned g_count[GRID_CELLS];
// Per-camera fused params: inv(post_rots)[9], post_trans[3], combine[9], trans[3]
__device__ float g_cam[NCAMS][24];

// ---------------------------------------------------------------------------
// Reciprocal without div.rn.f64: f32 estimate + 2 double Newton steps
// (< 1 double ulp — invisible after the final cast to f32).
__device__ __forceinline__ double rcp_newton(double d) {
    double r = (double)__frcp_rn((float)d);
    double e = fma(-d, r, 1.0);  r = fma(r, e, r);
    e        = fma(-d, r, 1.0);  r = fma(r, e, r);
    return r;
}

// ---------------------------------------------------------------------------
// Camera setup: 96 threads, one 3x3 inverse each, no f64 divides.
// PDL trigger at ENTRY: dependent blocks may launch immediately (fill blocks
// need no params; scatter blocks GridDependencySync before touching g_cam).
__global__ void cam_setup(const float* __restrict__ rots,
                          const float* __restrict__ trans,
                          const float* __restrict__ intrins,
                          const float* __restrict__ post_rots,
                          const float* __restrict__ post_trans) {
    cudaTriggerProgrammaticLaunchCompletion();
    __shared__ double sik[NCAMS][9];     // inv(intrins)
    int t = threadIdx.x;                 // 0..95
    int role = t / NCAMS;                // 0: post_rots, 1: intrins
    int cam  = t - role * NCAMS;

    if (t < 2 * NCAMS) {
        const float* src = (role == 0 ? post_rots : intrins) + cam * 9;
        double a[9];
        #pragma unroll
        for (int k = 0; k < 9; k++) a[k] = src[k];
        double det = a[0]*(a[4]*a[8] - a[5]*a[7])
                   + a[1]*(a[5]*a[6] - a[3]*a[8])
                   + a[2]*(a[3]*a[7] - a[4]*a[6]);
        double id = rcp_newton(det);
        #pragma unroll
        for (int r = 0; r < 3; r++) {
            #pragma unroll
            for (int c = 0; c < 3; c++) {
                int c1 = (c + 1) % 3, c2 = (c + 2) % 3;
                int r1 = (r + 1) % 3, r2 = (r + 2) % 3;
                double adj = a[c1*3 + r1] * a[c2*3 + r2]
                           - a[c1*3 + r2] * a[c2*3 + r1];
                double v = adj * id;
                if (role == 0) g_cam[cam][r*3 + c] = (float)v;
                else           sik[cam][r*3 + c]   = v;
            }
        }
        if (role == 0) {
            #pragma unroll
            for (int j = 0; j < 3; j++) {
                g_cam[cam][9 + j]  = post_trans[cam*3 + j];
                g_cam[cam][21 + j] = trans[cam*3 + j];
            }
        }
    }
    __syncthreads();
    if (t < NCAMS) {
        const float* rt = rots + t * 9;
        #pragma unroll
        for (int r = 0; r < 3; r++) {
            #pragma unroll
            for (int c = 0; c < 3; c++) {
                double s = (double)rt[r*3+0] * sik[t][0*3 + c]
                         + (double)rt[r*3+1] * sik[t][1*3 + c]
                         + (double)rt[r*3+2] * sik[t][2*3 + c];
                g_cam[t][12 + r*3 + c] = (float)s;
            }
        }
    }
}

// ---------------------------------------------------------------------------
// Fused output-zero-fill + voxelize + scatter-add.
// Blocks [0, FILL_BLOCKS) zero d_out (no camera dependency, no grid sync):
// they stream concurrently with cam_setup and the atomic phase.
// Remaining blocks: EIGHT lanes per point (each thread: 2 float4 loads +
// 2 vector REDs). Features are loaded ONLY for points that survive the cull
// (~20% of points) — culled warps skip all memory work.
__global__ void scatter(const float* __restrict__ x_feats,
                        float* __restrict__ out) {
    int tid = threadIdx.x;               // 256 threads
    int bid = blockIdx.x;

    if (bid < FILL_BLOCKS) {
        float4* o4 = reinterpret_cast<float4*>(out);
        float4 z4 = make_float4(0.f, 0.f, 0.f, 0.f);
        int base = bid * 4096 + tid;
        #pragma unroll
        for (int i = 0; i < 16; i++)
            __stcs(o4 + base + i * 256, z4);
        return;
    }

    cudaGridDependencySynchronize();    // wait for cam_setup's writes

    int gid = (bid - FILL_BLOCKS) * 256 + tid;   // exact grid, no guard
    int point = gid >> 3;
    int c8    = gid & 7;

    int cam = point / PTS_PER_CAM;
    int r   = point - cam * PTS_PER_CAM;
    int d   = r / (FHH * FWW);
    int r2  = r - d * (FHH * FWW);
    int h   = r2 / FWW;
    int w   = r2 - h * FWW;

    const float* cp = g_cam[cam];
    const float XSTEP = 351.0f / 21.0f;   // matches f32 linspace step
    const float YSTEP = 127.0f / 7.0f;
    float fx = (float)w * XSTEP;
    float fy = (float)h * YSTEP;
    float fz = 4.0f + (float)d;

    float px = fx - cp[9];
    float py = fy - cp[10];
    float pz = fz - cp[11];
    // q = inv(post_rots) @ p   (fma chain, k-order accumulation)
    float q0 = fmaf(cp[2], pz, fmaf(cp[1], py, cp[0]*px));
    float q1 = fmaf(cp[5], pz, fmaf(cp[4], py, cp[3]*px));
    float q2 = fmaf(cp[8], pz, fmaf(cp[7], py, cp[6]*px));
    // unproject: (u*d, v*d, d)
    float r0 = q0 * q2;
    float r1 = q1 * q2;
    float r2v = q2;
    // geom = combine @ r + trans
    float g0 = fmaf(cp[14], r2v, fmaf(cp[13], r1, cp[12]*r0)) + cp[21];
    float g1 = fmaf(cp[17], r2v, fmaf(cp[16], r1, cp[15]*r0)) + cp[22];
    float g2 = fmaf(cp[20], r2v, fmaf(cp[19], r1, cp[18]*r0)) + cp[23];

    // quantize: (geom - (BX - DX/2)) / DX, truncate toward zero
    float v0 = (g0 + 50.0f) / 0.5f;
    float v1 = (g1 + 50.0f) / 0.5f;
    float v2 = (g2 + 10.0f) / 20.0f;
    int i0 = (int)v0;
    int i1 = (int)v1;
    int i2 = (int)v2;

    if (i0 < 0 || i0 >= NXY || i1 < 0 || i1 >= NXY || i2 != 0) return;
    int b   = cam / NCAM;
    int vox = (b * NXY + i0) * NXY + i1;

    if (c8 == 0) g_count[vox] = 1u;   // benign race: all writers store 1

    // Features loaded only for kept points (~20%): 2 independent float4s.
    const float4* xf = reinterpret_cast<const float4*>(x_feats) + point * 16 + c8;
    float4 f0 = __ldcs(xf);
    float4 f1 = __ldcs(xf + 8);
    float* dst = g_scratch + (unsigned)vox * CC + c8 * 4;
    asm volatile("red.global.add.v4.f32 [%0], {%1,%2,%3,%4};"
                 :: "l"(dst), "f"(f0.x), "f"(f0.y), "f"(f0.z), "f"(f0.w)
                 : "memory");
    asm volatile("red.global.add.v4.f32 [%0], {%1,%2,%3,%4};"
                 :: "l"(dst + 32), "f"(f1.x), "f"(f1.y), "f"(f1.z), "f"(f1.w)
                 : "memory");
}

// ---------------------------------------------------------------------------
// Transpose [B,200(x),200(y),C] -> out [B,C,200(x),200(y)] — TOUCHED TILES
// ONLY. Untouched tiles were already zero-filled by scatter's fill blocks:
// skip read AND write. Touched cells are read once and zeroed behind the
// read (maintains the all-zero scratch invariant). g_count always cleared.
__global__ void transpose_out(float* __restrict__ out) {
    __shared__ float tile[2][32][65];
    __shared__ unsigned s_touch[2];
    int tid = threadIdx.x;               // 256 threads
    int xg  = blockIdx.y;                // 0..799 -> 2 consecutive bx
    int y0  = blockIdx.x * 32;
    int bx0 = xg * 2;
    int b   = bx0 / NXY;                 // 200 % 2 == 0: never crosses b
    int x0  = bx0 - b * NXY;

    cudaGridDependencySynchronize();    // wait for scatter's atomics/flags

    if (tid < 64) {
        int u  = tid >> 5;
        int yl = tid & 31;
        int y  = y0 + yl;
        unsigned fl = 0u;
        if (y < NXY) {
            int cell = (bx0 + u) * NXY + y;
            fl = g_count[cell];
            if (fl) g_count[cell] = 0u;
        }
        unsigned m = __ballot_sync(0xffffffffu, fl != 0u);
        if (yl == 0) s_touch[u] = m;
    }
    __syncthreads();

    if ((s_touch[0] | s_touch[1]) == 0u) return;   // fill already wrote zeros

    // Load phase: thread covers (c4, ylo) and (c4, ylo+16) for both rows.
    int c4  = tid & 15;
    int ylo = tid >> 4;                  // 0..15
    float4* sc4 = reinterpret_cast<float4*>(g_scratch);
    float4 z4 = make_float4(0.f, 0.f, 0.f, 0.f);
    #pragma unroll
    for (int u = 0; u < 2; u++) {
        unsigned m = s_touch[u];
        if (!m) continue;                // tile[u] stale; store phase skips it
        #pragma unroll
        for (int i = 0; i < 2; i++) {
            int yl = ylo + 16 * i;
            int yg = y0 + yl;
            bool live = (yg < NXY) && ((m >> yl) & 1u);
            float4 v = z4;
            unsigned idx = (unsigned)((bx0 + u) * NXY + yg) * 16 + c4;
            if (live) {
                v = __ldcs(sc4 + idx);
                __stcs(sc4 + idx, z4);
            }
            if (yg < NXY) {
                tile[u][yl][c4 * 4 + 0] = v.x;
                tile[u][yl][c4 * 4 + 1] = v.y;
                tile[u][yl][c4 * 4 + 2] = v.z;
                tile[u][yl][c4 * 4 + 3] = v.w;
            }
        }
    }
    __syncthreads();

    // Store phase: float4 along y, fully coalesced; conflict-free smem reads.
    int lane = tid & 31;
    int warp = tid >> 5;                 // 0..7
    int cgrp = lane >> 3;                // 0..3
    int yseg = lane & 7;                 // 0..7
    int yg4  = y0 + yseg * 4;
    float4* out4 = reinterpret_cast<float4*>(out);

    if (yg4 < NXY) {
        #pragma unroll
        for (int u = 0; u < 2; u++) {
            if (!s_touch[u]) continue;   // zeros already present from fill
            int x = x0 + u;
            #pragma unroll
            for (int j = 0; j < 2; j++) {
                int c = warp * 4 + cgrp + j * 32;
                int yl = yseg * 4;
                float4 v;
                v.x = tile[u][yl + 0][c];
                v.y = tile[u][yl + 1][c];
                v.z = tile[u][yl + 2][c];
                v.w = tile[u][yl + 3][c];
                unsigned o4 = ((((unsigned)b * CC + c) * NXY + x) * NXY + yg4) >> 2;
                __stcs(out4 + o4, v);
            }
        }
    }
}

// ---------------------------------------------------------------------------
extern "C" void kernel_launch(void* const* d_in, const int* in_sizes, int n_in,
                              void* d_out, int out_size) {
    const float* x_feats    = (const float*)d_in[0];
    const float* rots       = (const float*)d_in[1];
    const float* trans      = (const float*)d_in[2];
    const float* intrins    = (const float*)d_in[3];
    const float* post_rots  = (const float*)d_in[4];
    const float* post_trans = (const float*)d_in[5];
    float* out = (float*)d_out;

    cam_setup<<<1, 96>>>(rots, trans, intrins, post_rots, post_trans);

    cudaLaunchAttribute attrs[1];
    attrs[0].id = cudaLaunchAttributeProgrammaticStreamSerialization;
    attrs[0].val.programmaticStreamSerializationAllowed = 1;

    cudaLaunchConfig_t cfg = {};
    cfg.gridDim  = dim3(SCAT_BLOCKS + FILL_BLOCKS);
    cfg.blockDim = dim3(256);
    cfg.dynamicSmemBytes = 0;
    cfg.stream = 0;
    cfg.attrs = attrs;
    cfg.numAttrs = 1;
    cudaLaunchKernelEx(&cfg, scatter, x_feats, out);

    cudaLaunchConfig_t cfg2 = cfg;
    cfg2.gridDim = dim3(7, 800);
    cudaLaunchKernelEx(&cfg2, transpose_out, out);
}

// round 14
// speedup vs baseline: 2.6573x; 1.0623x over previous
#include <cuda_runtime.h>
#include <cuda_bf16.h>
#include <cstdint>

#define BB   8
#define NCAM 6
#define DD   41
#define FHH  8
#define FWW  22
#define CC   64
#define NXY  200
#define PTS_PER_CAM (DD*FHH*FWW)          /* 7216 */
#define NPTS (BB*NCAM*PTS_PER_CAM)        /* 346368 */
#define GRID_CELLS (BB*NXY*NXY)           /* 320000 */
#define NCAMS (BB*NCAM)                   /* 48 */
#define SCAT_BLOCKS (NPTS*4/256)          /* 5412: 4 lanes per point */
#define FILL_BLOCKS 1250                  /* 1250*4096 float4 = whole out */

// Scratch: channel-last voxel grid [B,200,200,C]  (81.92 MB, static device alloc)
// INVARIANT: all-zero at the start of every kernel_launch call. Static init
// zeroes it; transpose_out re-zeroes every touched cell after reading it.
__device__ float g_scratch[(size_t)GRID_CELLS * CC];
// Per-cell touched flag. INVARIANT: all-zero at call start; scatter sets,
// transpose_out reads + clears.
__device__ unsigned g_count[GRID_CELLS];
// Per-camera fused params: inv(post_rots)[9], post_trans[3], combine[9], trans[3]
__device__ float g_cam[NCAMS][24];

// ---------------------------------------------------------------------------
// Reciprocal without div.rn.f64: f32 estimate + 2 double Newton steps
// (< 1 double ulp — invisible after the final cast to f32).
__device__ __forceinline__ double rcp_newton(double d) {
    double r = (double)__frcp_rn((float)d);
    double e = fma(-d, r, 1.0);  r = fma(r, e, r);
    e        = fma(-d, r, 1.0);  r = fma(r, e, r);
    return r;
}

// ---------------------------------------------------------------------------
// Camera setup: 96 threads, one 3x3 inverse each, no f64 divides.
// PDL trigger at ENTRY: dependent blocks may launch immediately (fill blocks
// need no params; scatter blocks GridDependencySync before touching g_cam).
__global__ void cam_setup(const float* __restrict__ rots,
                          const float* __restrict__ trans,
                          const float* __restrict__ intrins,
                          const float* __restrict__ post_rots,
                          const float* __restrict__ post_trans) {
    cudaTriggerProgrammaticLaunchCompletion();
    __shared__ double sik[NCAMS][9];     // inv(intrins)
    int t = threadIdx.x;                 // 0..95
    int role = t / NCAMS;                // 0: post_rots, 1: intrins
    int cam  = t - role * NCAMS;

    if (t < 2 * NCAMS) {
        const float* src = (role == 0 ? post_rots : intrins) + cam * 9;
        double a[9];
        #pragma unroll
        for (int k = 0; k < 9; k++) a[k] = src[k];
        double det = a[0]*(a[4]*a[8] - a[5]*a[7])
                   + a[1]*(a[5]*a[6] - a[3]*a[8])
                   + a[2]*(a[3]*a[7] - a[4]*a[6]);
        double id = rcp_newton(det);
        #pragma unroll
        for (int r = 0; r < 3; r++) {
            #pragma unroll
            for (int c = 0; c < 3; c++) {
                int c1 = (c + 1) % 3, c2 = (c + 2) % 3;
                int r1 = (r + 1) % 3, r2 = (r + 2) % 3;
                double adj = a[c1*3 + r1] * a[c2*3 + r2]
                           - a[c1*3 + r2] * a[c2*3 + r1];
                double v = adj * id;
                if (role == 0) g_cam[cam][r*3 + c] = (float)v;
                else           sik[cam][r*3 + c]   = v;
            }
        }
        if (role == 0) {
            #pragma unroll
            for (int j = 0; j < 3; j++) {
                g_cam[cam][9 + j]  = post_trans[cam*3 + j];
                g_cam[cam][21 + j] = trans[cam*3 + j];
            }
        }
    }
    __syncthreads();
    if (t < NCAMS) {
        const float* rt = rots + t * 9;
        #pragma unroll
        for (int r = 0; r < 3; r++) {
            #pragma unroll
            for (int c = 0; c < 3; c++) {
                double s = (double)rt[r*3+0] * sik[t][0*3 + c]
                         + (double)rt[r*3+1] * sik[t][1*3 + c]
                         + (double)rt[r*3+2] * sik[t][2*3 + c];
                g_cam[t][12 + r*3 + c] = (float)s;
            }
        }
    }
}

// ---------------------------------------------------------------------------
// Fused output-zero-fill + voxelize + scatter-add.
// Blocks [0, FILL_BLOCKS) zero d_out (no camera dependency, no grid sync):
// they stream concurrently with cam_setup and the atomic phase.
// Remaining blocks: FOUR lanes per point (each thread: 4 float4 loads +
// 4 vector REDs). Features are loaded ONLY for points that survive the cull
// (~20% of points) — culled threads skip all memory work.
__global__ void scatter(const float* __restrict__ x_feats,
                        float* __restrict__ out) {
    int tid = threadIdx.x;               // 256 threads
    int bid = blockIdx.x;

    if (bid < FILL_BLOCKS) {
        float4* o4 = reinterpret_cast<float4*>(out);
        float4 z4 = make_float4(0.f, 0.f, 0.f, 0.f);
        int base = bid * 4096 + tid;
        #pragma unroll
        for (int i = 0; i < 16; i++)
            __stcs(o4 + base + i * 256, z4);
        return;
    }

    cudaGridDependencySynchronize();    // wait for cam_setup's writes

    int gid = (bid - FILL_BLOCKS) * 256 + tid;   // exact grid, no guard
    int point = gid >> 2;
    int c4    = gid & 3;                 // which quarter of the 64 channels

    int cam = point / PTS_PER_CAM;
    int r   = point - cam * PTS_PER_CAM;
    int d   = r / (FHH * FWW);
    int r2  = r - d * (FHH * FWW);
    int h   = r2 / FWW;
    int w   = r2 - h * FWW;

    const float* cp = g_cam[cam];
    const float XSTEP = 351.0f / 21.0f;   // matches f32 linspace step
    const float YSTEP = 127.0f / 7.0f;
    float fx = (float)w * XSTEP;
    float fy = (float)h * YSTEP;
    float fz = 4.0f + (float)d;

    float px = fx - cp[9];
    float py = fy - cp[10];
    float pz = fz - cp[11];
    // q = inv(post_rots) @ p   (fma chain, k-order accumulation)
    float q0 = fmaf(cp[2], pz, fmaf(cp[1], py, cp[0]*px));
    float q1 = fmaf(cp[5], pz, fmaf(cp[4], py, cp[3]*px));
    float q2 = fmaf(cp[8], pz, fmaf(cp[7], py, cp[6]*px));
    // unproject: (u*d, v*d, d)
    float r0 = q0 * q2;
    float r1 = q1 * q2;
    float r2v = q2;
    // geom = combine @ r + trans
    float g0 = fmaf(cp[14], r2v, fmaf(cp[13], r1, cp[12]*r0)) + cp[21];
    float g1 = fmaf(cp[17], r2v, fmaf(cp[16], r1, cp[15]*r0)) + cp[22];
    float g2 = fmaf(cp[20], r2v, fmaf(cp[19], r1, cp[18]*r0)) + cp[23];

    // quantize: (geom - (BX - DX/2)) / DX, truncate toward zero
    float v0 = (g0 + 50.0f) / 0.5f;
    float v1 = (g1 + 50.0f) / 0.5f;
    float v2 = (g2 + 10.0f) / 20.0f;
    int i0 = (int)v0;
    int i1 = (int)v1;
    int i2 = (int)v2;

    if (i0 < 0 || i0 >= NXY || i1 < 0 || i1 >= NXY || i2 != 0) return;
    int b   = cam / NCAM;
    int vox = (b * NXY + i0) * NXY + i1;

    if (c4 == 0) g_count[vox] = 1u;   // benign race: all writers store 1

    // Features loaded only for kept points: 4 independent float4s.
    const float4* xf = reinterpret_cast<const float4*>(x_feats) + point * 16 + c4;
    float4 f0 = __ldcs(xf);
    float4 f1 = __ldcs(xf + 4);
    float4 f2 = __ldcs(xf + 8);
    float4 f3 = __ldcs(xf + 12);
    float* dst = g_scratch + (unsigned)vox * CC + c4 * 4;
    asm volatile("red.global.add.v4.f32 [%0], {%1,%2,%3,%4};"
                 :: "l"(dst), "f"(f0.x), "f"(f0.y), "f"(f0.z), "f"(f0.w) : "memory");
    asm volatile("red.global.add.v4.f32 [%0], {%1,%2,%3,%4};"
                 :: "l"(dst + 16), "f"(f1.x), "f"(f1.y), "f"(f1.z), "f"(f1.w) : "memory");
    asm volatile("red.global.add.v4.f32 [%0], {%1,%2,%3,%4};"
                 :: "l"(dst + 32), "f"(f2.x), "f"(f2.y), "f"(f2.z), "f"(f2.w) : "memory");
    asm volatile("red.global.add.v4.f32 [%0], {%1,%2,%3,%4};"
                 :: "l"(dst + 48), "f"(f3.x), "f"(f3.y), "f"(f3.z), "f"(f3.w) : "memory");
}

// ---------------------------------------------------------------------------
// Transpose [B,200(x),200(y),C] -> out [B,C,200(x),200(y)] — TOUCHED TILES
// ONLY. Untouched tiles were already zero-filled by scatter's fill blocks:
// skip read AND write. Touched cells are read once and zeroed behind the
// read (maintains the all-zero scratch invariant). g_count always cleared.
__global__ void transpose_out(float* __restrict__ out) {
    __shared__ float tile[2][32][65];
    __shared__ unsigned s_touch[2];
    int tid = threadIdx.x;               // 256 threads
    int xg  = blockIdx.y;                // 0..799 -> 2 consecutive bx
    int y0  = blockIdx.x * 32;
    int bx0 = xg * 2;
    int b   = bx0 / NXY;                 // 200 % 2 == 0: never crosses b
    int x0  = bx0 - b * NXY;

    cudaGridDependencySynchronize();    // wait for scatter's atomics/flags

    if (tid < 64) {
        int u  = tid >> 5;
        int yl = tid & 31;
        int y  = y0 + yl;
        unsigned fl = 0u;
        if (y < NXY) {
            int cell = (bx0 + u) * NXY + y;
            fl = g_count[cell];
            if (fl) g_count[cell] = 0u;
        }
        unsigned m = __ballot_sync(0xffffffffu, fl != 0u);
        if (yl == 0) s_touch[u] = m;
    }
    __syncthreads();

    if ((s_touch[0] | s_touch[1]) == 0u) return;   // fill already wrote zeros

    // Load phase: thread covers (c4, ylo) and (c4, ylo+16) for both rows.
    int c4  = tid & 15;
    int ylo = tid >> 4;                  // 0..15
    float4* sc4 = reinterpret_cast<float4*>(g_scratch);
    float4 z4 = make_float4(0.f, 0.f, 0.f, 0.f);
    #pragma unroll
    for (int u = 0; u < 2; u++) {
        unsigned m = s_touch[u];
        if (!m) continue;                // tile[u] stale; store phase skips it
        #pragma unroll
        for (int i = 0; i < 2; i++) {
            int yl = ylo + 16 * i;
            int yg = y0 + yl;
            bool live = (yg < NXY) && ((m >> yl) & 1u);
            float4 v = z4;
            unsigned idx = (unsigned)((bx0 + u) * NXY + yg) * 16 + c4;
            if (live) {
                v = __ldcs(sc4 + idx);
                __stcs(sc4 + idx, z4);
            }
            if (yg < NXY) {
                tile[u][yl][c4 * 4 + 0] = v.x;
                tile[u][yl][c4 * 4 + 1] = v.y;
                tile[u][yl][c4 * 4 + 2] = v.z;
                tile[u][yl][c4 * 4 + 3] = v.w;
            }
        }
    }
    __syncthreads();

    // Store phase: float4 along y, fully coalesced; conflict-free smem reads.
    int lane = tid & 31;
    int warp = tid >> 5;                 // 0..7
    int cgrp = lane >> 3;                // 0..3
    int yseg = lane & 7;                 // 0..7
    int yg4  = y0 + yseg * 4;
    float4* out4 = reinterpret_cast<float4*>(out);

    if (yg4 < NXY) {
        #pragma unroll
        for (int u = 0; u < 2; u++) {
            if (!s_touch[u]) continue;   // zeros already present from fill
            int x = x0 + u;
            #pragma unroll
            for (int j = 0; j < 2; j++) {
                int c = warp * 4 + cgrp + j * 32;
                int yl = yseg * 4;
                float4 v;
                v.x = tile[u][yl + 0][c];
                v.y = tile[u][yl + 1][c];
                v.z = tile[u][yl + 2][c];
                v.w = tile[u][yl + 3][c];
                unsigned o4 = ((((unsigned)b * CC + c) * NXY + x) * NXY + yg4) >> 2;
                __stcs(out4 + o4, v);
            }
        }
    }
}

// ---------------------------------------------------------------------------
extern "C" void kernel_launch(void* const* d_in, const int* in_sizes, int n_in,
                              void* d_out, int out_size) {
    const float* x_feats    = (const float*)d_in[0];
    const float* rots       = (const float*)d_in[1];
    const float* trans      = (const float*)d_in[2];
    const float* intrins    = (const float*)d_in[3];
    const float* post_rots  = (const float*)d_in[4];
    const float* post_trans = (const float*)d_in[5];
    float* out = (float*)d_out;

    cam_setup<<<1, 96>>>(rots, trans, intrins, post_rots, post_trans);

    cudaLaunchAttribute attrs[1];
    attrs[0].id = cudaLaunchAttributeProgrammaticStreamSerialization;
    attrs[0].val.programmaticStreamSerializationAllowed = 1;

    cudaLaunchConfig_t cfg = {};
    cfg.gridDim  = dim3(SCAT_BLOCKS + FILL_BLOCKS);
    cfg.blockDim = dim3(256);
    cfg.dynamicSmemBytes = 0;
    cfg.stream = 0;
    cfg.attrs = attrs;
    cfg.numAttrs = 1;
    cudaLaunchKernelEx(&cfg, scatter, x_feats, out);

    cudaLaunchConfig_t cfg2 = cfg;
    cfg2.gridDim = dim3(7, 800);
    cudaLaunchKernelEx(&cfg2, transpose_out, out);
}